// round 6
// baseline (speedup 1.0000x reference)
#include <cuda_runtime.h>

// DAVIS346 voxelization constants
#define CW 346
#define CH 260
#define CC 16
#define NUM_VOX  (2 * CC * CH * CW)  // 2,877,440 floats
#define NUM_VOX4 (NUM_VOX / 4)       // 719,360 float4
#define TPB 256
#define NBLOCKS (148 * 4)            // one co-resident wave on 148 SMs

// Sense-reversing global barrier state. Static-initialized device globals
// (data, not allocation). Sense toggles per launch — valid across graph replays.
__device__ unsigned g_count = 0;
__device__ volatile unsigned g_sense = 0;

__device__ __forceinline__ void grid_barrier() {
    __syncthreads();
    if (threadIdx.x == 0) {
        unsigned s = g_sense;              // read pre-arrival sense
        __threadfence();                   // order zero-phase stores before arrive
        unsigned prev = atomicAdd(&g_count, 1u);
        if (prev == (unsigned)gridDim.x - 1u) {
            g_count = 0;                   // reset for next launch
            __threadfence();
            g_sense = s ^ 1u;              // release
        } else {
            while (g_sense == s) { __nanosleep(64); }
        }
        __threadfence();                   // acquire before scatter stores
    }
    __syncthreads();
}

__global__ __launch_bounds__(TPB)
void vox_fused_kernel(const float4* __restrict__ ev,
                      float* __restrict__ out, int n) {
    const int tid  = threadIdx.x;
    const int gtid = blockIdx.x * TPB + tid;
    const int T    = NBLOCKS * TPB;        // total threads

    // ---- Phase A: zero the output (harness poisons d_out) ----
    float4* out4 = (float4*)out;
    #pragma unroll 2
    for (int i = gtid; i < NUM_VOX4; i += T)
        out4[i] = make_float4(0.f, 0.f, 0.f, 0.f);

    // ---- Prefetch iteration 0's events (overlaps zero-phase drain) ----
    int base0 = blockIdx.x * (TPB * 2) + tid;
    float4 p0 = (base0 < n)       ? __ldcs(&ev[base0])       : make_float4(0.f, 0.f, -1.f, 0.f);
    float4 p1 = (base0 + TPB < n) ? __ldcs(&ev[base0 + TPB]) : make_float4(0.f, 0.f, -1.f, 0.f);

    // ---- Global barrier: all zeroing visible before any scatter store ----
    grid_barrier();

    // ---- Phase B: scatter 1.0f per event, 2 events/thread/iteration ----
    const int step = T * 2;
    for (int base = base0; base < n; base += step) {
        float4 e0, e1;
        if (base == base0) { e0 = p0; e1 = p1; }
        else {
            e0 = (base < n)       ? __ldcs(&ev[base])       : make_float4(0.f, 0.f, -1.f, 0.f);
            e1 = (base + TPB < n) ? __ldcs(&ev[base + TPB]) : make_float4(0.f, 0.f, -1.f, 0.f);
        }

        // idx = x + 346*y + 346*260*((ceil(16t)-1) + 16*(p>0)); exact in fp32 (<2^24)
        float fb0 = ceilf(e0.z * (float)CC) - 1.0f + ((e0.w > 0.0f) ? (float)CC : 0.0f);
        float fb1 = ceilf(e1.z * (float)CC) - 1.0f + ((e1.w > 0.0f) ? (float)CC : 0.0f);
        int idx0 = (int)fmaf((float)(CW * CH), fb0, fmaf((float)CW, e0.y, e0.x));
        int idx1 = (int)fmaf((float)(CW * CH), fb1, fmaf((float)CW, e1.y, e1.x));
        bool v0 = (e0.z > 0.0f) && (e0.z <= 1.0f);
        bool v1 = (e1.z > 0.0f) && (e1.z <= 1.0f);

        if (v0) out[idx0] = 1.0f;   // non-accumulating scatter, races benign
        if (v1) out[idx1] = 1.0f;
    }
}

extern "C" void kernel_launch(void* const* d_in, const int* in_sizes, int n_in,
                              void* d_out, int out_size) {
    const float4* ev = (const float4*)d_in[0];
    float* out = (float*)d_out;
    int n = in_sizes[0] / 4;               // events are [N,4] float32

    vox_fused_kernel<<<NBLOCKS, TPB>>>(ev, out, n);
}

// round 7
// speedup vs baseline: 1.0276x; 1.0276x over previous
#include <cuda_runtime.h>

// DAVIS346 voxelization constants
#define CW 346
#define CH 260
#define CC 16
#define NUM_VOX  (2 * CC * CH * CW)  // 2,877,440 floats
#define NUM_VOX4 (NUM_VOX / 4)       // 719,360 float4
#define TPB 256

// Sense-reversing global barrier state (device globals = data, not allocation).
__device__ unsigned g_count = 0;
__device__ volatile unsigned g_sense = 0;

__device__ __forceinline__ void grid_barrier() {
    __syncthreads();
    if (threadIdx.x == 0) {
        unsigned s = g_sense;              // pre-arrival sense
        __threadfence();                   // zero-phase stores visible before arrive
        unsigned prev = atomicAdd(&g_count, 1u);
        if (prev == (unsigned)gridDim.x - 1u) {
            g_count = 0;                   // reset for next replay
            __threadfence();
            g_sense = s ^ 1u;              // release
        } else {
            while (g_sense == s) { __nanosleep(32); }
        }
        __threadfence();                   // acquire before scatter stores
    }
    __syncthreads();
}

__global__ __launch_bounds__(TPB, 8)     // force <=32 regs -> 8 CTAs/SM co-resident
void vox_fused_kernel(const float4* __restrict__ ev,
                      float* __restrict__ out, int n) {
    const int tid  = threadIdx.x;
    const int T    = gridDim.x * TPB;    // total threads (one resident wave)
    const int gtid = blockIdx.x * TPB + tid;

    // ---- Phase A: zero the output (harness poisons d_out) ----
    float4* out4 = (float4*)out;
    for (int i = gtid; i < NUM_VOX4; i += T)
        out4[i] = make_float4(0.f, 0.f, 0.f, 0.f);

    // ---- Prefetch iteration 0 (overlaps zero-phase drain + barrier) ----
    const int base0 = blockIdx.x * (TPB * 2) + tid;
    float4 p0 = (base0 < n)       ? __ldcs(&ev[base0])       : make_float4(0.f, 0.f, -1.f, 0.f);
    float4 p1 = (base0 + TPB < n) ? __ldcs(&ev[base0 + TPB]) : make_float4(0.f, 0.f, -1.f, 0.f);

    // ---- Global barrier: all zeroing visible before any scatter store ----
    grid_barrier();

    // ---- Phase B: scatter 1.0f per event, 2 events/thread/iteration ----
    const int step = T * 2;
    for (int base = base0; base < n; base += step) {
        float4 e0, e1;
        if (base == base0) { e0 = p0; e1 = p1; }
        else {
            e0 = (base < n)       ? __ldcs(&ev[base])       : make_float4(0.f, 0.f, -1.f, 0.f);
            e1 = (base + TPB < n) ? __ldcs(&ev[base + TPB]) : make_float4(0.f, 0.f, -1.f, 0.f);
        }

        // idx = x + 346*y + 346*260*((ceil(16t)-1) + 16*(p>0)); exact in fp32 (<2^24)
        float fb0 = ceilf(e0.z * (float)CC) - 1.0f + ((e0.w > 0.0f) ? (float)CC : 0.0f);
        float fb1 = ceilf(e1.z * (float)CC) - 1.0f + ((e1.w > 0.0f) ? (float)CC : 0.0f);
        int idx0 = (int)fmaf((float)(CW * CH), fb0, fmaf((float)CW, e0.y, e0.x));
        int idx1 = (int)fmaf((float)(CW * CH), fb1, fmaf((float)CW, e1.y, e1.x));
        bool v0 = (e0.z > 0.0f) && (e0.z <= 1.0f);
        bool v1 = (e1.z > 0.0f) && (e1.z <= 1.0f);

        if (v0) out[idx0] = 1.0f;   // non-accumulating scatter, races benign
        if (v1) out[idx1] = 1.0f;
    }
}

extern "C" void kernel_launch(void* const* d_in, const int* in_sizes, int n_in,
                              void* d_out, int out_size) {
    const float4* ev = (const float4*)d_in[0];
    float* out = (float*)d_out;
    int n = in_sizes[0] / 4;              // events are [N,4] float32

    // One fully co-resident wave, sized by the occupancy API (deadlock-safe).
    int dev = 0, sms = 0, perSM = 0;
    cudaGetDevice(&dev);
    cudaDeviceGetAttribute(&sms, cudaDevAttrMultiProcessorCount, dev);
    cudaOccupancyMaxActiveBlocksPerMultiprocessor(&perSM, vox_fused_kernel, TPB, 0);
    if (perSM < 1) perSM = 1;
    int blocks = sms * perSM;             // expected 148 * 8 = 1184

    vox_fused_kernel<<<blocks, TPB>>>(ev, out, n);
}

// round 8
// speedup vs baseline: 1.0470x; 1.0189x over previous
#include <cuda_runtime.h>

// DAVIS346 voxelization constants
#define CW 346
#define CH 260
#define CC 16
#define NUM_VOX  (2 * CC * CH * CW)  // 2,877,440 floats
#define NUM_VOX4 (NUM_VOX / 4)       // 719,360 float4
#define TPB 256

#define SENTINEL make_float4(0.f, 0.f, -1.f, 0.f)

// Sense-reversing global barrier state (device globals = data, not allocation).
__device__ unsigned g_count = 0;
__device__ volatile unsigned g_sense = 0;

__device__ __forceinline__ void grid_barrier() {
    __syncthreads();
    if (threadIdx.x == 0) {
        unsigned s = g_sense;              // pre-arrival sense
        __threadfence();                   // zero-phase stores visible before arrive
        unsigned prev = atomicAdd(&g_count, 1u);
        if (prev == (unsigned)gridDim.x - 1u) {
            g_count = 0;                   // reset for next replay
            __threadfence();
            g_sense = s ^ 1u;              // release
        } else {
            while (g_sense == s) { __nanosleep(32); }
        }
        __threadfence();                   // acquire before scatter stores
    }
    __syncthreads();
}

__global__ __launch_bounds__(TPB, 8)
void vox_fused_kernel(const float4* __restrict__ ev,
                      float* __restrict__ out, int n) {
    const int tid  = threadIdx.x;
    const int T    = gridDim.x * TPB;    // total threads (one resident wave)
    const int gtid = blockIdx.x * TPB + tid;

    // ---- Phase A: zero the output (harness poisons d_out) ----
    float4* out4 = (float4*)out;
    for (int i = gtid; i < NUM_VOX4; i += T)
        out4[i] = make_float4(0.f, 0.f, 0.f, 0.f);

    // ---- Prefetch iteration 0 (in flight across zero drain + barrier) ----
    const int base0 = blockIdx.x * (TPB * 2) + tid;
    const int step  = T * 2;
    float4 c0 = (base0 < n)       ? __ldcs(&ev[base0])       : SENTINEL;
    float4 c1 = (base0 + TPB < n) ? __ldcs(&ev[base0 + TPB]) : SENTINEL;

    // ---- Global barrier: all zeroing visible before any scatter store ----
    grid_barrier();

    // ---- Phase B: software-pipelined scatter, 2 events/thread/iter ----
    // Next iteration's loads are issued BEFORE current iteration's consume,
    // so load latency is hidden behind a full iteration of store issue.
    for (int base = base0; base < n; base += step) {
        const int nb = base + step;
        float4 n0 = (nb < n)       ? __ldcs(&ev[nb])       : SENTINEL;
        float4 n1 = (nb + TPB < n) ? __ldcs(&ev[nb + TPB]) : SENTINEL;

        // idx = x + 346*y + 346*260*((ceil(16t)-1) + 16*(p>0)); exact fp32 (<2^24)
        float fb0 = ceilf(c0.z * (float)CC) - 1.0f + ((c0.w > 0.0f) ? (float)CC : 0.0f);
        float fb1 = ceilf(c1.z * (float)CC) - 1.0f + ((c1.w > 0.0f) ? (float)CC : 0.0f);
        int idx0 = (int)fmaf((float)(CW * CH), fb0, fmaf((float)CW, c0.y, c0.x));
        int idx1 = (int)fmaf((float)(CW * CH), fb1, fmaf((float)CW, c1.y, c1.x));
        bool v0 = (c0.z > 0.0f) && (c0.z <= 1.0f);
        bool v1 = (c1.z > 0.0f) && (c1.z <= 1.0f);

        if (v0) out[idx0] = 1.0f;   // non-accumulating scatter, races benign
        if (v1) out[idx1] = 1.0f;

        c0 = n0;
        c1 = n1;
    }
}

extern "C" void kernel_launch(void* const* d_in, const int* in_sizes, int n_in,
                              void* d_out, int out_size) {
    const float4* ev = (const float4*)d_in[0];
    float* out = (float*)d_out;
    int n = in_sizes[0] / 4;              // events are [N,4] float32

    // One fully co-resident wave (deadlock-safe via occupancy API).
    int dev = 0, sms = 0, perSM = 0;
    cudaGetDevice(&dev);
    cudaDeviceGetAttribute(&sms, cudaDevAttrMultiProcessorCount, dev);
    cudaOccupancyMaxActiveBlocksPerMultiprocessor(&perSM, vox_fused_kernel, TPB, 0);
    if (perSM < 1) perSM = 1;
    int blocks = sms * perSM;

    vox_fused_kernel<<<blocks, TPB>>>(ev, out, n);
}

// round 9
// speedup vs baseline: 1.1804x; 1.1274x over previous
#include <cuda_runtime.h>

// DAVIS346 voxelization constants
#define CW 346
#define CH 260
#define CC 16
#define NUM_VOX  (2 * CC * CH * CW)   // 2,877,440 floats
#define NUM_VOX4 (NUM_VOX / 4)        // 719,360 float4
#define EV_PER_THREAD 2
#define TPB 256

__global__ __launch_bounds__(TPB)
void vox_zero_kernel(float4* __restrict__ out) {
    int i = blockIdx.x * TPB + threadIdx.x;
    if (i < NUM_VOX4) out[i] = make_float4(0.f, 0.f, 0.f, 0.f);
    // Signal the dependent scatter launch as early as possible: this CTA's
    // stores are issued; PDL's sync semantics guarantee visibility once all
    // CTAs have triggered.
    cudaTriggerProgrammaticLaunchCompletion();
}

__global__ __launch_bounds__(TPB)
void vox_scatter_kernel(const float4* __restrict__ ev,
                        float* __restrict__ out, int n) {
    int base = blockIdx.x * (TPB * EV_PER_THREAD) + threadIdx.x;

    // Two independent streaming loads (MLP=2): proven optimum (EV1/2/4/8 sweep).
    float4 e0 = (base < n)       ? __ldcs(&ev[base])       : make_float4(0.f, 0.f, -1.f, 0.f);
    float4 e1 = (base + TPB < n) ? __ldcs(&ev[base + TPB]) : make_float4(0.f, 0.f, -1.f, 0.f);

    // idx = x + 346*y + 346*260*((ceil(16t)-1) + 16*(p>0)); exact in fp32 (<2^24)
    float fb0 = ceilf(e0.z * (float)CC) - 1.0f + ((e0.w > 0.0f) ? (float)CC : 0.0f);
    float fb1 = ceilf(e1.z * (float)CC) - 1.0f + ((e1.w > 0.0f) ? (float)CC : 0.0f);
    int idx0 = (int)fmaf((float)(CW * CH), fb0, fmaf((float)CW, e0.y, e0.x));
    int idx1 = (int)fmaf((float)(CW * CH), fb1, fmaf((float)CW, e1.y, e1.x));
    bool v0 = (e0.z > 0.0f) && (e0.z <= 1.0f);
    bool v1 = (e1.z > 0.0f) && (e1.z <= 1.0f);

    // PDL: the event loads above ran concurrently with the zero kernel;
    // stores must wait until every zero-CTA has triggered (stores visible).
    cudaGridDependencySynchronize();

    if (v0) out[idx0] = 1.0f;   // non-accumulating scatter, races benign
    if (v1) out[idx1] = 1.0f;
}

extern "C" void kernel_launch(void* const* d_in, const int* in_sizes, int n_in,
                              void* d_out, int out_size) {
    const float4* ev = (const float4*)d_in[0];
    float* out = (float*)d_out;
    int n = in_sizes[0] / 4;              // events are [N,4] float32

    // 1) zero the output (harness poisons d_out) — PDL primary
    int zb = (NUM_VOX4 + TPB - 1) / TPB;
    vox_zero_kernel<<<zb, TPB>>>((float4*)out);

    // 2) scatter — PDL secondary: launches early, loads overlap the zeroing
    int blocks = (n + TPB * EV_PER_THREAD - 1) / (TPB * EV_PER_THREAD);
    cudaLaunchConfig_t cfg = {};
    cfg.gridDim  = dim3(blocks, 1, 1);
    cfg.blockDim = dim3(TPB, 1, 1);
    cfg.dynamicSmemBytes = 0;
    cfg.stream = 0;
    cudaLaunchAttribute attr[1];
    attr[0].id = cudaLaunchAttributeProgrammaticStreamSerialization;
    attr[0].val.programmaticStreamSerializationAllowed = 1;
    cfg.attrs = attr;
    cfg.numAttrs = 1;
    cudaLaunchKernelEx(&cfg, vox_scatter_kernel, ev, out, n);
}